// round 11
// baseline (speedup 1.0000x reference)
#include <cuda_runtime.h>
#include <cuda_bf16.h>
#include <math.h>
#include <math_constants.h>
#include <cstdint>

#define BB 4
#define SS 2048
#define DM 1024
#define HH 16
#define DKK 64
#define MTOT (BB*SS)   // 8192

// ---------------- scratch (allocation-free) ----------------
__device__ __nv_bfloat16 g_xh[(size_t)MTOT*DM],  g_xl[(size_t)MTOT*DM];
__device__ __nv_bfloat16 g_aoh[(size_t)MTOT*DM], g_aol[(size_t)MTOT*DM];
__device__ __nv_bfloat16 g_wh[(size_t)4*DM*DM],  g_wl[(size_t)4*DM*DM];
__device__ __nv_bfloat16 g_Qh[(size_t)BB*HH*SS*DKK], g_Ql[(size_t)BB*HH*SS*DKK];
__device__ __nv_bfloat16 g_Kh[(size_t)BB*HH*SS*DKK], g_Kl[(size_t)BB*HH*SS*DKK];
__device__ __nv_bfloat16 g_Vh[(size_t)BB*HH*SS*DKK], g_Vl[(size_t)BB*HH*SS*DKK];
__device__ float g_rope[SS*64];   // [s][0..31]=cos, [s][32..63]=sin

#define ASCALE 0.1803368801111244f   // 1/sqrt(64)*log2(e)

// ---------------- PTX helpers ----------------
__device__ __forceinline__ uint32_t smem_to_u32(const void* p) {
    uint32_t a;
    asm("{ .reg .u64 t; cvta.to.shared.u64 t, %1; cvt.u32.u64 %0, t; }"
        : "=r"(a) : "l"(p));
    return a;
}
__device__ __forceinline__ void cp16(uint32_t dst, const void* src) {
    asm volatile("cp.async.cg.shared.global [%0], [%1], 16;"
                 :: "r"(dst), "l"(src) : "memory");
}
#define CP_COMMIT() asm volatile("cp.async.commit_group;" ::: "memory")
#define CP_WAIT1()  asm volatile("cp.async.wait_group 1;"  ::: "memory")
#define CP_WAIT0()  asm volatile("cp.async.wait_group 0;"  ::: "memory")

__device__ __forceinline__ void ldsm4(uint32_t* r, uint32_t addr) {
    asm volatile("ldmatrix.sync.aligned.m8n8.x4.shared.b16 {%0,%1,%2,%3}, [%4];"
                 : "=r"(r[0]), "=r"(r[1]), "=r"(r[2]), "=r"(r[3]) : "r"(addr));
}
__device__ __forceinline__ void ldsm4t(uint32_t* r, uint32_t addr) {
    asm volatile("ldmatrix.sync.aligned.m8n8.x4.trans.shared.b16 {%0,%1,%2,%3}, [%4];"
                 : "=r"(r[0]), "=r"(r[1]), "=r"(r[2]), "=r"(r[3]) : "r"(addr));
}
__device__ __forceinline__ void mma16816(float* d, const uint32_t* a,
                                         uint32_t b0, uint32_t b1) {
    asm volatile("mma.sync.aligned.m16n8k16.row.col.f32.bf16.bf16.f32 "
                 "{%0,%1,%2,%3}, {%4,%5,%6,%7}, {%8,%9}, {%0,%1,%2,%3};"
                 : "+f"(d[0]), "+f"(d[1]), "+f"(d[2]), "+f"(d[3])
                 : "r"(a[0]), "r"(a[1]), "r"(a[2]), "r"(a[3]), "r"(b0), "r"(b1));
}
__device__ __forceinline__ float ex2(float x) {
    float y;
    asm("ex2.approx.f32 %0, %1;" : "=f"(y) : "f"(x));
    return y;
}
__device__ __forceinline__ uint32_t packbf(float lo, float hi) {
    uint32_t r;
    asm("cvt.rn.bf16x2.f32 %0, %1, %2;" : "=r"(r) : "f"(hi), "f"(lo));
    return r;
}
__device__ __forceinline__ void split2(float d0, float d1, uint32_t& uh, uint32_t& ul) {
    uh = packbf(d0, d1);
    float h0 = __uint_as_float(uh << 16);
    float h1 = __uint_as_float(uh & 0xffff0000u);
    ul = packbf(d0 - h0, d1 - h1);
}

// ---------------------------------------------------------------------------
// fp32 -> (bf16 hi, bf16 lo) splits
// ---------------------------------------------------------------------------
__global__ void split_kernel(const float* __restrict__ src,
                             __nv_bfloat16* __restrict__ hi,
                             __nv_bfloat16* __restrict__ lo, int n4)
{
    int i = blockIdx.x * blockDim.x + threadIdx.x;
    if (i >= n4) return;
    float4 v = ((const float4*)src)[i];
    uint32_t h0, l0, h1, l1;
    split2(v.x, v.y, h0, l0);
    split2(v.z, v.w, h1, l1);
    ((uint2*)hi)[i] = make_uint2(h0, h1);
    ((uint2*)lo)[i] = make_uint2(l0, l1);
}

__global__ void split_w_kernel(const float* __restrict__ w0, const float* __restrict__ w1,
                               const float* __restrict__ w2, const float* __restrict__ w3,
                               __nv_bfloat16* __restrict__ hi,
                               __nv_bfloat16* __restrict__ lo)
{
    const int wsel = blockIdx.y;
    const float* src = (wsel == 0) ? w0 : (wsel == 1) ? w1 : (wsel == 2) ? w2 : w3;
    size_t off = (size_t)wsel * (DM * DM / 4);
    int i = blockIdx.x * blockDim.x + threadIdx.x;
    float4 v = ((const float4*)src)[i];
    uint32_t h0, l0, h1, l1;
    split2(v.x, v.y, h0, l0);
    split2(v.z, v.w, h1, l1);
    ((uint2*)hi)[off + i] = make_uint2(h0, h1);
    ((uint2*)lo)[off + i] = make_uint2(l0, l1);
}

__global__ void rope_init_kernel(const int* __restrict__ tokpos, float* __restrict__ rope)
{
    int idx = blockIdx.x * blockDim.x + threadIdx.x;
    int s = idx >> 5, p = idx & 31;
    float fr = (float)exp2(-(double)p * (13.287712379549449 / 32.0));
    float ang = (float)tokpos[s] * fr;
    float sn, cs;
    sincosf(ang, &sn, &cs);
    rope[s * 64 + p] = cs;
    rope[s * 64 + 32 + p] = sn;
}

// ---------------------------------------------------------------------------
// bf16x3 mma.sync GEMM, CTA tile 256x128, BK=32, 512 threads, warp grid 4x4,
// warp tile 64x32 (2x MMAs per LDSM byte vs previous 128x128/32x64 layout).
// 2-stage cp.async, single sync per K-chunk, pitch-80 smem (conflict-free).
// ---------------------------------------------------------------------------
#define A_T   (256*80)            // 20480
#define B_T   (128*80)            // 10240
#define STG   (2*A_T + 2*B_T)     // 61440
#define GSMEM (2*STG)             // 122880

__device__ __forceinline__ void issue_stage(uint32_t sdst,
    const __nv_bfloat16* __restrict__ Ah, const __nv_bfloat16* __restrict__ Al,
    const __nv_bfloat16* __restrict__ Bh, const __nv_bfloat16* __restrict__ Bl,
    int m0, int n0, int kc, int tid)
{
    const int colb = kc * 64;
#pragma unroll
    for (int it = 0; it < 2; it++) {
        int idx = tid + it * 512;          // 0..1023  (A: 256 rows x 4 chunks)
        int row = idx >> 2;
        int ch  = (idx & 3) * 16;
        uint32_t soff = row * 80 + ch;
        cp16(sdst + soff,       (const char*)(Ah + (size_t)(m0 + row) * DM) + colb + ch);
        cp16(sdst + A_T + soff, (const char*)(Al + (size_t)(m0 + row) * DM) + colb + ch);
    }
    {
        int row = tid >> 2;                // 0..127  (B: 128 rows x 4 chunks)
        int ch  = (tid & 3) * 16;
        uint32_t soff = row * 80 + ch;
        cp16(sdst + 2 * A_T + soff,       (const char*)(Bh + (size_t)(n0 + row) * DM) + colb + ch);
        cp16(sdst + 2 * A_T + B_T + soff, (const char*)(Bl + (size_t)(n0 + row) * DM) + colb + ch);
    }
}

__global__ __launch_bounds__(512, 1)
void gemm_mma(const __nv_bfloat16* __restrict__ Ah, const __nv_bfloat16* __restrict__ Al,
              const __nv_bfloat16* __restrict__ WhBase, const __nv_bfloat16* __restrict__ WlBase,
              float* __restrict__ out,
              __nv_bfloat16* __restrict__ qh, __nv_bfloat16* __restrict__ ql,
              __nv_bfloat16* __restrict__ kh, __nv_bfloat16* __restrict__ kl,
              __nv_bfloat16* __restrict__ vvh, __nv_bfloat16* __restrict__ vvl,
              const float* __restrict__ rope, int wo)
{
    extern __shared__ char smc[];
    const uint32_t sbase = smem_to_u32(smc);

    const int tid  = threadIdx.x;
    const int wid  = tid >> 5;
    const int lane = tid & 31;
    const int m0 = blockIdx.x * 256;
    const int by = blockIdx.y;
    const int wsel = wo ? 3 : (by >> 3);
    const int n0 = wo ? by * 128 : (by & 7) * 128;
    const __nv_bfloat16* Bh = WhBase + (size_t)wsel * DM * DM;
    const __nv_bfloat16* Bl = WlBase + (size_t)wsel * DM * DM;

    const int wm = (wid & 3) * 64;    // 4 warp rows, 64 M each
    const int wn = (wid >> 2) * 32;   // 4 warp cols, 32 N each

    float acc[4][4][4];               // [mt][nj][q]
#pragma unroll
    for (int i = 0; i < 4; i++)
#pragma unroll
        for (int j = 0; j < 4; j++)
#pragma unroll
            for (int q = 0; q < 4; q++) acc[i][j][q] = 0.f;

    const uint32_t lrow = (lane & 7) + ((lane >> 3) & 1) * 8;
    const uint32_t kbl  = ((lane >> 4) & 1) * 16;

    issue_stage(sbase, Ah, Al, Bh, Bl, m0, n0, 0, tid);
    CP_COMMIT();

    const int NKC = DM / 32;   // 32
    for (int kc = 0; kc < NKC; kc++) {
        CP_WAIT0();
        __syncthreads();
        if (kc + 1 < NKC) {
            issue_stage(sbase + ((kc + 1) & 1) * STG, Ah, Al, Bh, Bl,
                        m0, n0, kc + 1, tid);
            CP_COMMIT();
        }

        const uint32_t sb = sbase + (kc & 1) * STG;
#pragma unroll
        for (int ks = 0; ks < 2; ks++) {
            const uint32_t kb = ks * 32 + kbl;
            uint32_t ah[4][4], al[4][4];
#pragma unroll
            for (int mt = 0; mt < 4; mt++) {
                const uint32_t aadr = sb + (wm + mt * 16 + lrow) * 80 + kb;
                ldsm4(ah[mt], aadr);
                ldsm4(al[mt], aadr + A_T);
            }
#pragma unroll
            for (int nt = 0; nt < 2; nt++) {
                uint32_t bhf[4], blf[4];
                const uint32_t badr = sb + 2 * A_T + (wn + nt * 16 + lrow) * 80 + kb;
                ldsm4(bhf, badr);
                ldsm4(blf, badr + B_T);
#pragma unroll
                for (int term = 0; term < 3; term++) {
#pragma unroll
                    for (int sel = 0; sel < 2; sel++) {
                        const int nj = nt * 2 + sel;
                        const uint32_t b0 = (term == 1) ? blf[sel]     : bhf[sel];
                        const uint32_t b1 = (term == 1) ? blf[sel + 2] : bhf[sel + 2];
#pragma unroll
                        for (int mt = 0; mt < 4; mt++) {
                            const uint32_t* a = (term == 2) ? al[mt] : ah[mt];
                            mma16816(acc[mt][nj], a, b0, b1);
                        }
                    }
                }
            }
        }
    }

    // ---- epilogue ----
    __nv_bfloat16 *oh = qh, *ol = ql;
    if (wsel == 1) { oh = kh; ol = kl; }
    else if (wsel == 2) { oh = vvh; ol = vvl; }

    const int g = lane >> 2;
    const int t2 = (lane & 3) * 2;
#pragma unroll
    for (int mt = 0; mt < 4; mt++) {
#pragma unroll
        for (int half = 0; half < 2; half++) {
            const int r = m0 + wm + mt * 16 + half * 8 + g;
            const int b = r >> 11;
            const int s = r & 2047;
#pragma unroll
            for (int nj = 0; nj < 4; nj++) {
                const int e = n0 + wn + nj * 8 + t2;
                float d0 = acc[mt][nj][half * 2 + 0];
                float d1 = acc[mt][nj][half * 2 + 1];
                if (wsel == 3) {
                    *(float2*)&out[(size_t)r * DM + e] = make_float2(d0, d1);
                } else {
                    const int h  = e >> 6;
                    const int dk = e & 63;
                    if (wsel <= 1) {
                        const int p = dk >> 1;
                        float cs = __ldg(&rope[s * 64 + p]);
                        float sn = __ldg(&rope[s * 64 + 32 + p]);
                        float r0 = d0 * cs - d1 * sn;
                        float r1 = d0 * sn + d1 * cs;
                        d0 = r0; d1 = r1;
                        if (wsel == 0) { d0 *= ASCALE; d1 *= ASCALE; }
                    }
                    size_t idx = ((size_t)(b * HH + h) * SS + s) * DKK + dk;
                    uint32_t uh, ul;
                    split2(d0, d1, uh, ul);
                    *(uint32_t*)&oh[idx] = uh;
                    *(uint32_t*)&ol[idx] = ul;
                }
            }
        }
    }
}

// ---------------------------------------------------------------------------
// Tensor-core flash attention (bf16x3, causal), 2-stage KV, 2 CTAs/SM.
// Unchanged (validated).
// ---------------------------------------------------------------------------
#define AP      144
#define QT_B    (128*AP)      // 18432
#define KT_B    (64*AP)       // 9216
#define ASTG_B  (4*KT_B)      // 36864
#define ASMEM   (2*QT_B + 2*ASTG_B)   // 110592

__device__ __forceinline__ void issue_kv(uint32_t dst,
    const __nv_bfloat16* __restrict__ Kh, const __nv_bfloat16* __restrict__ Kl,
    const __nv_bfloat16* __restrict__ Vh, const __nv_bfloat16* __restrict__ Vl,
    size_t base, int kb, int tid)
{
#pragma unroll
    for (int it = 0; it < 8; it++) {
        int f   = tid + it * 256;
        int ten = f >> 9;
        int row = (f >> 3) & 63;
        int ch  = f & 7;
        const __nv_bfloat16* sp = (ten == 0) ? Kh : (ten == 1) ? Kl
                                 : (ten == 2) ? Vh : Vl;
        sp += base + (size_t)(kb * 64 + row) * DKK + ch * 8;
        cp16(dst + ten * KT_B + row * AP + ch * 16, sp);
    }
}

__global__ __launch_bounds__(256, 2)
void attn_mma(const __nv_bfloat16* __restrict__ Qh, const __nv_bfloat16* __restrict__ Ql,
              const __nv_bfloat16* __restrict__ Kh, const __nv_bfloat16* __restrict__ Kl,
              const __nv_bfloat16* __restrict__ Vh, const __nv_bfloat16* __restrict__ Vl,
              __nv_bfloat16* __restrict__ AOh, __nv_bfloat16* __restrict__ AOl)
{
    extern __shared__ char smc[];
    const uint32_t sb = smem_to_u32(smc);
    const uint32_t sQ  = sb;
    const uint32_t sKV = sb + 2 * QT_B;

    const int tid  = threadIdx.x;
    const int wid  = tid >> 5;
    const int lane = tid & 31;
    const int g = lane >> 2;
    const int t = lane & 3;

    const int qb = 15 - (blockIdx.x >> 6);
    const int bh = blockIdx.x & 63;
    const size_t base = (size_t)bh * SS * DKK;
    const int nkb = 2 * qb + 2;

    const float NINF = __int_as_float(0xff800000);

#pragma unroll
    for (int it = 0; it < 8; it++) {
        int f   = tid + it * 256;
        int ten = f >> 10;
        int row = (f >> 3) & 127;
        int ch  = f & 7;
        const __nv_bfloat16* sp = (ten ? Ql : Qh)
            + base + (size_t)(qb * 128 + row) * DKK + ch * 8;
        cp16(sQ + ten * QT_B + row * AP + ch * 16, sp);
    }
    issue_kv(sKV, Kh, Kl, Vh, Vl, base, 0, tid);
    CP_COMMIT();
    issue_kv(sKV + ASTG_B, Kh, Kl, Vh, Vl, base, 1, tid);
    CP_COMMIT();

    CP_WAIT1();
    __syncthreads();

    const uint32_t lrow = (lane & 7) + ((lane >> 3) & 1) * 8;
    const uint32_t kb16 = ((lane >> 4) & 1) * 16;
    uint32_t qfh[4][4], qfl[4][4];
#pragma unroll
    for (int ks = 0; ks < 4; ks++) {
        uint32_t a = sQ + (wid * 16 + lrow) * AP + ks * 32 + kb16;
        ldsm4(qfh[ks], a);
        ldsm4(qfl[ks], a + QT_B);
    }

    float oacc[8][4];
#pragma unroll
    for (int nj = 0; nj < 8; nj++)
#pragma unroll
        for (int q = 0; q < 4; q++) oacc[nj][q] = 0.f;
    float m0 = NINF, m1 = NINF, l0 = 0.f, l1 = 0.f;

    const int r0 = qb * 128 + wid * 16 + g;
    const int r1 = r0 + 8;

    const uint32_t vrow = (lane & 7) + ((lane >> 4) & 1) * 8;
    const uint32_t vb16 = ((lane >> 3) & 1) * 16;

    for (int kb = 0; kb < nkb; kb++) {
        if (kb + 1 < nkb) CP_WAIT1(); else CP_WAIT0();
        __syncthreads();

        const uint32_t sK = sKV + (kb & 1) * ASTG_B;
        const uint32_t sV = sK + 2 * KT_B;

        float sf[8][4];
#pragma unroll
        for (int nj = 0; nj < 8; nj++)
#pragma unroll
            for (int q = 0; q < 4; q++) sf[nj][q] = 0.f;

#pragma unroll
        for (int ks = 0; ks < 4; ks++) {
#pragma unroll
            for (int ntp = 0; ntp < 2; ntp++) {
                uint32_t kfh[2][4], kfl[2][4];
#pragma unroll
                for (int nt2 = 0; nt2 < 2; nt2++) {
                    uint32_t ba = sK + ((ntp * 2 + nt2) * 16 + lrow) * AP + ks * 32 + kb16;
                    ldsm4(kfh[nt2], ba);
                    ldsm4(kfl[nt2], ba + KT_B);
                }
#pragma unroll
                for (int term = 0; term < 3; term++) {
                    const uint32_t* a = (term == 2) ? qfl[ks] : qfh[ks];
#pragma unroll
                    for (int nt2 = 0; nt2 < 2; nt2++) {
#pragma unroll
                        for (int sel = 0; sel < 2; sel++) {
                            const int nj = (ntp * 2 + nt2) * 2 + sel;
                            const uint32_t b0 = (term == 1) ? kfl[nt2][sel]     : kfh[nt2][sel];
                            const uint32_t b1 = (term == 1) ? kfl[nt2][sel + 2] : kfh[nt2][sel + 2];
                            mma16816(sf[nj], a, b0, b1);
                        }
                    }
                }
            }
        }

        if (kb >= 2 * qb) {
#pragma unroll
            for (int nj = 0; nj < 8; nj++) {
                int c0 = kb * 64 + nj * 8 + 2 * t;
                if (c0 > r0)     sf[nj][0] = NINF;
                if (c0 + 1 > r0) sf[nj][1] = NINF;
                if (c0 > r1)     sf[nj][2] = NINF;
                if (c0 + 1 > r1) sf[nj][3] = NINF;
            }
        }

        float mx0 = sf[0][0], mx1 = sf[0][2];
#pragma unroll
        for (int nj = 0; nj < 8; nj++) {
            mx0 = fmaxf(mx0, fmaxf(sf[nj][0], sf[nj][1]));
            mx1 = fmaxf(mx1, fmaxf(sf[nj][2], sf[nj][3]));
        }
        mx0 = fmaxf(mx0, __shfl_xor_sync(0xffffffffu, mx0, 1));
        mx0 = fmaxf(mx0, __shfl_xor_sync(0xffffffffu, mx0, 2));
        mx1 = fmaxf(mx1, __shfl_xor_sync(0xffffffffu, mx1, 1));
        mx1 = fmaxf(mx1, __shfl_xor_sync(0xffffffffu, mx1, 2));
        float mn0 = fmaxf(m0, mx0), mn1 = fmaxf(m1, mx1);
        float al0 = ex2(m0 - mn0), al1 = ex2(m1 - mn1);
        m0 = mn0; m1 = mn1;

        float s0 = 0.f, s1 = 0.f;
#pragma unroll
        for (int nj = 0; nj < 8; nj++) {
            sf[nj][0] = ex2(sf[nj][0] - m0);
            sf[nj][1] = ex2(sf[nj][1] - m0);
            sf[nj][2] = ex2(sf[nj][2] - m1);
            sf[nj][3] = ex2(sf[nj][3] - m1);
            s0 += sf[nj][0] + sf[nj][1];
            s1 += sf[nj][2] + sf[nj][3];
        }
        s0 += __shfl_xor_sync(0xffffffffu, s0, 1);
        s0 += __shfl_xor_sync(0xffffffffu, s0, 2);
        s1 += __shfl_xor_sync(0xffffffffu, s1, 1);
        s1 += __shfl_xor_sync(0xffffffffu, s1, 2);
        l0 = l0 * al0 + s0;
        l1 = l1 * al1 + s1;

#pragma unroll
        for (int nj = 0; nj < 8; nj++) {
            oacc[nj][0] *= al0; oacc[nj][1] *= al0;
            oacc[nj][2] *= al1; oacc[nj][3] *= al1;
        }

#pragma unroll
        for (int ks = 0; ks < 4; ks++) {
            uint32_t pah[4], pal[4];
            split2(sf[2 * ks][0],     sf[2 * ks][1],     pah[0], pal[0]);
            split2(sf[2 * ks][2],     sf[2 * ks][3],     pah[1], pal[1]);
            split2(sf[2 * ks + 1][0], sf[2 * ks + 1][1], pah[2], pal[2]);
            split2(sf[2 * ks + 1][2], sf[2 * ks + 1][3], pah[3], pal[3]);
#pragma unroll
            for (int ntp = 0; ntp < 2; ntp++) {
                uint32_t vfh[2][4], vfl[2][4];
#pragma unroll
                for (int nt2 = 0; nt2 < 2; nt2++) {
                    uint32_t va = sV + (ks * 16 + vrow) * AP + (ntp * 2 + nt2) * 32 + vb16;
                    ldsm4t(vfh[nt2], va);
                    ldsm4t(vfl[nt2], va + KT_B);
                }
#pragma unroll
                for (int term = 0; term < 3; term++) {
                    const uint32_t* a = (term == 2) ? pal : pah;
#pragma unroll
                    for (int nt2 = 0; nt2 < 2; nt2++) {
#pragma unroll
                        for (int sel = 0; sel < 2; sel++) {
                            const int nj = (ntp * 2 + nt2) * 2 + sel;
                            const uint32_t b0 = (term == 1) ? vfl[nt2][sel]     : vfh[nt2][sel];
                            const uint32_t b1 = (term == 1) ? vfl[nt2][sel + 2] : vfh[nt2][sel + 2];
                            mma16816(oacc[nj], a, b0, b1);
                        }
                    }
                }
            }
        }
        __syncthreads();

        if (kb + 2 < nkb) {
            issue_kv(sKV + (kb & 1) * ASTG_B, Kh, Kl, Vh, Vl, base, kb + 2, tid);
            CP_COMMIT();
        }
    }

    // ---- epilogue ----
    const float inv0 = 1.0f / l0;
    const float inv1 = 1.0f / l1;
    const int b = bh >> 4, h = bh & 15;
    const size_t row0 = (size_t)(b * SS + r0) * DM;
    const size_t row1 = (size_t)(b * SS + r1) * DM;
#pragma unroll
    for (int nj = 0; nj < 8; nj++) {
        const int e = h * 64 + nj * 8 + 2 * t;
        uint32_t uh, ul;
        split2(oacc[nj][0] * inv0, oacc[nj][1] * inv0, uh, ul);
        *(uint32_t*)&AOh[row0 + e] = uh;
        *(uint32_t*)&AOl[row0 + e] = ul;
        split2(oacc[nj][2] * inv1, oacc[nj][3] * inv1, uh, ul);
        *(uint32_t*)&AOh[row1 + e] = uh;
        *(uint32_t*)&AOl[row1 + e] = ul;
    }
}

// ---------------------------------------------------------------------------
extern "C" void kernel_launch(void* const* d_in, const int* in_sizes, int n_in,
                              void* d_out, int out_size)
{
    const float* x  = (const float*)d_in[0];
    const float* Wq = (const float*)d_in[1];
    const float* Wk = (const float*)d_in[2];
    const float* Wv = (const float*)d_in[3];
    const float* Wo = (const float*)d_in[4];
    const int*   tp = (const int*)  d_in[5];
    float* out = (float*)d_out;

    float* gRope;
    __nv_bfloat16 *xh, *xl, *wh, *wl, *aoh, *aol;
    __nv_bfloat16 *qh, *ql, *kh, *kl, *vh, *vl;
    cudaGetSymbolAddress((void**)&gRope, g_rope);
    cudaGetSymbolAddress((void**)&xh,  g_xh);
    cudaGetSymbolAddress((void**)&xl,  g_xl);
    cudaGetSymbolAddress((void**)&wh,  g_wh);
    cudaGetSymbolAddress((void**)&wl,  g_wl);
    cudaGetSymbolAddress((void**)&aoh, g_aoh);
    cudaGetSymbolAddress((void**)&aol, g_aol);
    cudaGetSymbolAddress((void**)&qh,  g_Qh);
    cudaGetSymbolAddress((void**)&ql,  g_Ql);
    cudaGetSymbolAddress((void**)&kh,  g_Kh);
    cudaGetSymbolAddress((void**)&kl,  g_Kl);
    cudaGetSymbolAddress((void**)&vh,  g_Vh);
    cudaGetSymbolAddress((void**)&vl,  g_Vl);

    cudaFuncSetAttribute(gemm_mma, cudaFuncAttributeMaxDynamicSharedMemorySize, GSMEM);
    cudaFuncSetAttribute(attn_mma, cudaFuncAttributeMaxDynamicSharedMemorySize, ASMEM);

    const int nx4 = MTOT * DM / 4;
    const int nw4 = DM * DM / 4;
    split_kernel<<<nx4 / 256, 256>>>(x, xh, xl, nx4);
    dim3 wgrid(nw4 / 256, 4);
    split_w_kernel<<<wgrid, 256>>>(Wq, Wk, Wv, Wo, wh, wl);
    rope_init_kernel<<<SS * 32 / 256, 256>>>(tp, gRope);

    dim3 qkvgrid(MTOT / 256, 24);   // (32, 24)
    gemm_mma<<<qkvgrid, 512, GSMEM>>>(xh, xl, wh, wl, nullptr,
                                      qh, ql, kh, kl, vh, vl, gRope, 0);

    attn_mma<<<1024, 256, ASMEM>>>(qh, ql, kh, kl, vh, vl, aoh, aol);

    dim3 wogrid(MTOT / 256, 8);     // (32, 8)
    gemm_mma<<<wogrid, 512, GSMEM>>>(aoh, aol, wh, wl, out,
                                     qh, ql, kh, kl, vh, vl, gRope, 1);
}

// round 12
// speedup vs baseline: 1.0687x; 1.0687x over previous
#include <cuda_runtime.h>
#include <cuda_bf16.h>
#include <math.h>
#include <math_constants.h>
#include <cstdint>

#define BB 4
#define SS 2048
#define DM 1024
#define HH 16
#define DKK 64
#define MTOT (BB*SS)   // 8192

// ---------------- scratch (allocation-free) ----------------
__device__ __nv_bfloat16 g_xh[(size_t)MTOT*DM],  g_xl[(size_t)MTOT*DM];
__device__ __nv_bfloat16 g_aoh[(size_t)MTOT*DM], g_aol[(size_t)MTOT*DM];
__device__ __nv_bfloat16 g_wh[(size_t)4*DM*DM],  g_wl[(size_t)4*DM*DM];
__device__ __nv_bfloat16 g_Qh[(size_t)BB*HH*SS*DKK], g_Ql[(size_t)BB*HH*SS*DKK];
__device__ __nv_bfloat16 g_Kh[(size_t)BB*HH*SS*DKK], g_Kl[(size_t)BB*HH*SS*DKK];
__device__ __nv_bfloat16 g_Vh[(size_t)BB*HH*SS*DKK], g_Vl[(size_t)BB*HH*SS*DKK];
__device__ float g_rope[SS*64];   // [s][0..31]=cos, [s][32..63]=sin

#define ASCALE 0.1803368801111244f   // 1/sqrt(64)*log2(e)

// ---------------- PTX helpers ----------------
__device__ __forceinline__ uint32_t smem_to_u32(const void* p) {
    uint32_t a;
    asm("{ .reg .u64 t; cvta.to.shared.u64 t, %1; cvt.u32.u64 %0, t; }"
        : "=r"(a) : "l"(p));
    return a;
}
__device__ __forceinline__ void cp16(uint32_t dst, const void* src) {
    asm volatile("cp.async.cg.shared.global [%0], [%1], 16;"
                 :: "r"(dst), "l"(src) : "memory");
}
#define CP_COMMIT() asm volatile("cp.async.commit_group;" ::: "memory")
#define CP_WAIT1()  asm volatile("cp.async.wait_group 1;"  ::: "memory")
#define CP_WAIT0()  asm volatile("cp.async.wait_group 0;"  ::: "memory")

__device__ __forceinline__ void ldsm4(uint32_t* r, uint32_t addr) {
    asm volatile("ldmatrix.sync.aligned.m8n8.x4.shared.b16 {%0,%1,%2,%3}, [%4];"
                 : "=r"(r[0]), "=r"(r[1]), "=r"(r[2]), "=r"(r[3]) : "r"(addr));
}
__device__ __forceinline__ void ldsm4t(uint32_t* r, uint32_t addr) {
    asm volatile("ldmatrix.sync.aligned.m8n8.x4.trans.shared.b16 {%0,%1,%2,%3}, [%4];"
                 : "=r"(r[0]), "=r"(r[1]), "=r"(r[2]), "=r"(r[3]) : "r"(addr));
}
__device__ __forceinline__ void mma16816(float* d, const uint32_t* a,
                                         uint32_t b0, uint32_t b1) {
    asm volatile("mma.sync.aligned.m16n8k16.row.col.f32.bf16.bf16.f32 "
                 "{%0,%1,%2,%3}, {%4,%5,%6,%7}, {%8,%9}, {%0,%1,%2,%3};"
                 : "+f"(d[0]), "+f"(d[1]), "+f"(d[2]), "+f"(d[3])
                 : "r"(a[0]), "r"(a[1]), "r"(a[2]), "r"(a[3]), "r"(b0), "r"(b1));
}
__device__ __forceinline__ float ex2(float x) {
    float y;
    asm("ex2.approx.f32 %0, %1;" : "=f"(y) : "f"(x));
    return y;
}
__device__ __forceinline__ uint32_t packbf(float lo, float hi) {
    uint32_t r;
    asm("cvt.rn.bf16x2.f32 %0, %1, %2;" : "=r"(r) : "f"(hi), "f"(lo));
    return r;
}
__device__ __forceinline__ void split2(float d0, float d1, uint32_t& uh, uint32_t& ul) {
    uh = packbf(d0, d1);
    float h0 = __uint_as_float(uh << 16);
    float h1 = __uint_as_float(uh & 0xffff0000u);
    ul = packbf(d0 - h0, d1 - h1);
}

// ---------------------------------------------------------------------------
// fp32 -> (bf16 hi, bf16 lo) splits
// ---------------------------------------------------------------------------
__global__ void split_kernel(const float* __restrict__ src,
                             __nv_bfloat16* __restrict__ hi,
                             __nv_bfloat16* __restrict__ lo, int n4)
{
    int i = blockIdx.x * blockDim.x + threadIdx.x;
    if (i >= n4) return;
    float4 v = ((const float4*)src)[i];
    uint32_t h0, l0, h1, l1;
    split2(v.x, v.y, h0, l0);
    split2(v.z, v.w, h1, l1);
    ((uint2*)hi)[i] = make_uint2(h0, h1);
    ((uint2*)lo)[i] = make_uint2(l0, l1);
}

__global__ void split_w_kernel(const float* __restrict__ w0, const float* __restrict__ w1,
                               const float* __restrict__ w2, const float* __restrict__ w3,
                               __nv_bfloat16* __restrict__ hi,
                               __nv_bfloat16* __restrict__ lo)
{
    const int wsel = blockIdx.y;
    const float* src = (wsel == 0) ? w0 : (wsel == 1) ? w1 : (wsel == 2) ? w2 : w3;
    size_t off = (size_t)wsel * (DM * DM / 4);
    int i = blockIdx.x * blockDim.x + threadIdx.x;
    float4 v = ((const float4*)src)[i];
    uint32_t h0, l0, h1, l1;
    split2(v.x, v.y, h0, l0);
    split2(v.z, v.w, h1, l1);
    ((uint2*)hi)[off + i] = make_uint2(h0, h1);
    ((uint2*)lo)[off + i] = make_uint2(l0, l1);
}

__global__ void rope_init_kernel(const int* __restrict__ tokpos, float* __restrict__ rope)
{
    int idx = blockIdx.x * blockDim.x + threadIdx.x;
    int s = idx >> 5, p = idx & 31;
    float fr = (float)exp2(-(double)p * (13.287712379549449 / 32.0));
    float ang = (float)tokpos[s] * fr;
    float sn, cs;
    sincosf(ang, &sn, &cs);
    rope[s * 64 + p] = cs;
    rope[s * 64 + 32 + p] = sn;
}

// ---------------------------------------------------------------------------
// bf16x3 mma.sync GEMM, CTA 128x128, BK=32, 2-stage, 2 CTAs/SM.
// Warp grid 2x4 (warp tile 64x32): 96 MMAs per 24 LDSM.x4 (2x better than
// the 32x64 layout) while keeping 2 CTAs/SM.
// ---------------------------------------------------------------------------
#define GP      40
#define TILE_B  (128*GP*2)         // 10240
#define STAGE_B (4*TILE_B)         // 40960
#define GSMEM   (2*STAGE_B)        // 81920

__device__ __forceinline__ void issue_stage(uint32_t sdst,
    const __nv_bfloat16* __restrict__ Ah, const __nv_bfloat16* __restrict__ Al,
    const __nv_bfloat16* __restrict__ Bh, const __nv_bfloat16* __restrict__ Bl,
    int m0, int n0, int kc, int tid)
{
    const int colb = kc * 64;
#pragma unroll
    for (int it = 0; it < 2; it++) {
        int idx = tid + it * 256;
        int row = idx >> 2;
        int ch  = (idx & 3) * 16;
        uint32_t soff = row * 80 + ch;
        const char* pa = (const char*)(Ah + (size_t)(m0 + row) * DM) + colb + ch;
        const char* pl = (const char*)(Al + (size_t)(m0 + row) * DM) + colb + ch;
        const char* pb = (const char*)(Bh + (size_t)(n0 + row) * DM) + colb + ch;
        const char* pc = (const char*)(Bl + (size_t)(n0 + row) * DM) + colb + ch;
        cp16(sdst + 0 * TILE_B + soff, pa);
        cp16(sdst + 1 * TILE_B + soff, pl);
        cp16(sdst + 2 * TILE_B + soff, pb);
        cp16(sdst + 3 * TILE_B + soff, pc);
    }
}

__global__ __launch_bounds__(256, 2)
void gemm_mma(const __nv_bfloat16* __restrict__ Ah, const __nv_bfloat16* __restrict__ Al,
              const __nv_bfloat16* __restrict__ WhBase, const __nv_bfloat16* __restrict__ WlBase,
              float* __restrict__ out,
              __nv_bfloat16* __restrict__ qh, __nv_bfloat16* __restrict__ ql,
              __nv_bfloat16* __restrict__ kh, __nv_bfloat16* __restrict__ kl,
              __nv_bfloat16* __restrict__ vvh, __nv_bfloat16* __restrict__ vvl,
              const float* __restrict__ rope, int wo)
{
    extern __shared__ char smc[];
    const uint32_t sbase = smem_to_u32(smc);

    const int tid  = threadIdx.x;
    const int wid  = tid >> 5;
    const int lane = tid & 31;
    const int m0 = blockIdx.x * 128;
    const int by = blockIdx.y;
    const int wsel = wo ? 3 : (by >> 3);
    const int n0 = wo ? by * 128 : (by & 7) * 128;
    const __nv_bfloat16* Bh = WhBase + (size_t)wsel * DM * DM;
    const __nv_bfloat16* Bl = WlBase + (size_t)wsel * DM * DM;

    const int wm = (wid & 1) * 64;    // 2 warp rows x 64 M
    const int wn = (wid >> 1) * 32;   // 4 warp cols x 32 N

    float acc[4][4][4];               // [mt][nj][q]
#pragma unroll
    for (int i = 0; i < 4; i++)
#pragma unroll
        for (int j = 0; j < 4; j++)
#pragma unroll
            for (int q = 0; q < 4; q++) acc[i][j][q] = 0.f;

    const uint32_t lrow = (lane & 7) + ((lane >> 3) & 1) * 8;
    const uint32_t kbl  = ((lane >> 4) & 1) * 16;

    issue_stage(sbase, Ah, Al, Bh, Bl, m0, n0, 0, tid);
    CP_COMMIT();

    const int NKC = DM / 32;   // 32
    for (int kc = 0; kc < NKC; kc++) {
        CP_WAIT0();
        __syncthreads();
        if (kc + 1 < NKC) {
            issue_stage(sbase + ((kc + 1) & 1) * STAGE_B, Ah, Al, Bh, Bl,
                        m0, n0, kc + 1, tid);
            CP_COMMIT();
        }

        const uint32_t sb = sbase + (kc & 1) * STAGE_B;
#pragma unroll
        for (int ks = 0; ks < 2; ks++) {
            const uint32_t kb = ks * 32 + kbl;
            uint32_t ah[4][4], al[4][4];
#pragma unroll
            for (int mt = 0; mt < 4; mt++) {
                const uint32_t aadr = sb + (wm + mt * 16 + lrow) * 80 + kb;
                ldsm4(ah[mt], aadr);
                ldsm4(al[mt], aadr + TILE_B);
            }
#pragma unroll
            for (int nt = 0; nt < 2; nt++) {
                uint32_t bhf[4], blf[4];
                const uint32_t badr = sb + 2 * TILE_B + (wn + nt * 16 + lrow) * 80 + kb;
                ldsm4(bhf, badr);
                ldsm4(blf, badr + TILE_B);
#pragma unroll
                for (int term = 0; term < 3; term++) {
#pragma unroll
                    for (int sel = 0; sel < 2; sel++) {
                        const int nj = nt * 2 + sel;
                        const uint32_t b0 = (term == 1) ? blf[sel]     : bhf[sel];
                        const uint32_t b1 = (term == 1) ? blf[sel + 2] : bhf[sel + 2];
#pragma unroll
                        for (int mt = 0; mt < 4; mt++) {
                            const uint32_t* a = (term == 2) ? al[mt] : ah[mt];
                            mma16816(acc[mt][nj], a, b0, b1);
                        }
                    }
                }
            }
        }
    }

    // ---- epilogue ----
    __nv_bfloat16 *oh = qh, *ol = ql;
    if (wsel == 1) { oh = kh; ol = kl; }
    else if (wsel == 2) { oh = vvh; ol = vvl; }

    const int g = lane >> 2;
    const int t2 = (lane & 3) * 2;
#pragma unroll
    for (int mt = 0; mt < 4; mt++) {
#pragma unroll
        for (int half = 0; half < 2; half++) {
            const int r = m0 + wm + mt * 16 + half * 8 + g;
            const int b = r >> 11;
            const int s = r & 2047;
#pragma unroll
            for (int nj = 0; nj < 4; nj++) {
                const int e = n0 + wn + nj * 8 + t2;
                float d0 = acc[mt][nj][half * 2 + 0];
                float d1 = acc[mt][nj][half * 2 + 1];
                if (wsel == 3) {
                    *(float2*)&out[(size_t)r * DM + e] = make_float2(d0, d1);
                } else {
                    const int h  = e >> 6;
                    const int dk = e & 63;
                    if (wsel <= 1) {
                        const int p = dk >> 1;
                        float cs = __ldg(&rope[s * 64 + p]);
                        float sn = __ldg(&rope[s * 64 + 32 + p]);
                        float r0 = d0 * cs - d1 * sn;
                        float r1 = d0 * sn + d1 * cs;
                        d0 = r0; d1 = r1;
                        if (wsel == 0) { d0 *= ASCALE; d1 *= ASCALE; }
                    }
                    size_t idx = ((size_t)(b * HH + h) * SS + s) * DKK + dk;
                    uint32_t uh, ul;
                    split2(d0, d1, uh, ul);
                    *(uint32_t*)&oh[idx] = uh;
                    *(uint32_t*)&ol[idx] = ul;
                }
            }
        }
    }
}

// ---------------------------------------------------------------------------
// Tensor-core flash attention (bf16x3, causal), 2-stage KV, 2 CTAs/SM.
// Unchanged (validated, 1013 µs config).
// ---------------------------------------------------------------------------
#define AP      144
#define QT_B    (128*AP)      // 18432
#define KT_B    (64*AP)       // 9216
#define ASTG_B  (4*KT_B)      // 36864
#define ASMEM   (2*QT_B + 2*ASTG_B)   // 110592

__device__ __forceinline__ void issue_kv(uint32_t dst,
    const __nv_bfloat16* __restrict__ Kh, const __nv_bfloat16* __restrict__ Kl,
    const __nv_bfloat16* __restrict__ Vh, const __nv_bfloat16* __restrict__ Vl,
    size_t base, int kb, int tid)
{
#pragma unroll
    for (int it = 0; it < 8; it++) {
        int f   = tid + it * 256;
        int ten = f >> 9;
        int row = (f >> 3) & 63;
        int ch  = f & 7;
        const __nv_bfloat16* sp = (ten == 0) ? Kh : (ten == 1) ? Kl
                                 : (ten == 2) ? Vh : Vl;
        sp += base + (size_t)(kb * 64 + row) * DKK + ch * 8;
        cp16(dst + ten * KT_B + row * AP + ch * 16, sp);
    }
}

__global__ __launch_bounds__(256, 2)
void attn_mma(const __nv_bfloat16* __restrict__ Qh, const __nv_bfloat16* __restrict__ Ql,
              const __nv_bfloat16* __restrict__ Kh, const __nv_bfloat16* __restrict__ Kl,
              const __nv_bfloat16* __restrict__ Vh, const __nv_bfloat16* __restrict__ Vl,
              __nv_bfloat16* __restrict__ AOh, __nv_bfloat16* __restrict__ AOl)
{
    extern __shared__ char smc[];
    const uint32_t sb = smem_to_u32(smc);
    const uint32_t sQ  = sb;
    const uint32_t sKV = sb + 2 * QT_B;

    const int tid  = threadIdx.x;
    const int wid  = tid >> 5;
    const int lane = tid & 31;
    const int g = lane >> 2;
    const int t = lane & 3;

    const int qb = 15 - (blockIdx.x >> 6);
    const int bh = blockIdx.x & 63;
    const size_t base = (size_t)bh * SS * DKK;
    const int nkb = 2 * qb + 2;

    const float NINF = __int_as_float(0xff800000);

#pragma unroll
    for (int it = 0; it < 8; it++) {
        int f   = tid + it * 256;
        int ten = f >> 10;
        int row = (f >> 3) & 127;
        int ch  = f & 7;
        const __nv_bfloat16* sp = (ten ? Ql : Qh)
            + base + (size_t)(qb * 128 + row) * DKK + ch * 8;
        cp16(sQ + ten * QT_B + row * AP + ch * 16, sp);
    }
    issue_kv(sKV, Kh, Kl, Vh, Vl, base, 0, tid);
    CP_COMMIT();
    issue_kv(sKV + ASTG_B, Kh, Kl, Vh, Vl, base, 1, tid);
    CP_COMMIT();

    CP_WAIT1();
    __syncthreads();

    const uint32_t lrow = (lane & 7) + ((lane >> 3) & 1) * 8;
    const uint32_t kb16 = ((lane >> 4) & 1) * 16;
    uint32_t qfh[4][4], qfl[4][4];
#pragma unroll
    for (int ks = 0; ks < 4; ks++) {
        uint32_t a = sQ + (wid * 16 + lrow) * AP + ks * 32 + kb16;
        ldsm4(qfh[ks], a);
        ldsm4(qfl[ks], a + QT_B);
    }

    float oacc[8][4];
#pragma unroll
    for (int nj = 0; nj < 8; nj++)
#pragma unroll
        for (int q = 0; q < 4; q++) oacc[nj][q] = 0.f;
    float m0 = NINF, m1 = NINF, l0 = 0.f, l1 = 0.f;

    const int r0 = qb * 128 + wid * 16 + g;
    const int r1 = r0 + 8;

    const uint32_t vrow = (lane & 7) + ((lane >> 4) & 1) * 8;
    const uint32_t vb16 = ((lane >> 3) & 1) * 16;

    for (int kb = 0; kb < nkb; kb++) {
        if (kb + 1 < nkb) CP_WAIT1(); else CP_WAIT0();
        __syncthreads();

        const uint32_t sK = sKV + (kb & 1) * ASTG_B;
        const uint32_t sV = sK + 2 * KT_B;

        float sf[8][4];
#pragma unroll
        for (int nj = 0; nj < 8; nj++)
#pragma unroll
            for (int q = 0; q < 4; q++) sf[nj][q] = 0.f;

#pragma unroll
        for (int ks = 0; ks < 4; ks++) {
#pragma unroll
            for (int ntp = 0; ntp < 2; ntp++) {
                uint32_t kfh[2][4], kfl[2][4];
#pragma unroll
                for (int nt2 = 0; nt2 < 2; nt2++) {
                    uint32_t ba = sK + ((ntp * 2 + nt2) * 16 + lrow) * AP + ks * 32 + kb16;
                    ldsm4(kfh[nt2], ba);
                    ldsm4(kfl[nt2], ba + KT_B);
                }
#pragma unroll
                for (int term = 0; term < 3; term++) {
                    const uint32_t* a = (term == 2) ? qfl[ks] : qfh[ks];
#pragma unroll
                    for (int nt2 = 0; nt2 < 2; nt2++) {
#pragma unroll
                        for (int sel = 0; sel < 2; sel++) {
                            const int nj = (ntp * 2 + nt2) * 2 + sel;
                            const uint32_t b0 = (term == 1) ? kfl[nt2][sel]     : kfh[nt2][sel];
                            const uint32_t b1 = (term == 1) ? kfl[nt2][sel + 2] : kfh[nt2][sel + 2];
                            mma16816(sf[nj], a, b0, b1);
                        }
                    }
                }
            }
        }

        if (kb >= 2 * qb) {
#pragma unroll
            for (int nj = 0; nj < 8; nj++) {
                int c0 = kb * 64 + nj * 8 + 2 * t;
                if (c0 > r0)     sf[nj][0] = NINF;
                if (c0 + 1 > r0) sf[nj][1] = NINF;
                if (c0 > r1)     sf[nj][2] = NINF;
                if (c0 + 1 > r1) sf[nj][3] = NINF;
            }
        }

        float mx0 = sf[0][0], mx1 = sf[0][2];
#pragma unroll
        for (int nj = 0; nj < 8; nj++) {
            mx0 = fmaxf(mx0, fmaxf(sf[nj][0], sf[nj][1]));
            mx1 = fmaxf(mx1, fmaxf(sf[nj][2], sf[nj][3]));
        }
        mx0 = fmaxf(mx0, __shfl_xor_sync(0xffffffffu, mx0, 1));
        mx0 = fmaxf(mx0, __shfl_xor_sync(0xffffffffu, mx0, 2));
        mx1 = fmaxf(mx1, __shfl_xor_sync(0xffffffffu, mx1, 1));
        mx1 = fmaxf(mx1, __shfl_xor_sync(0xffffffffu, mx1, 2));
        float mn0 = fmaxf(m0, mx0), mn1 = fmaxf(m1, mx1);
        float al0 = ex2(m0 - mn0), al1 = ex2(m1 - mn1);
        m0 = mn0; m1 = mn1;

        float s0 = 0.f, s1 = 0.f;
#pragma unroll
        for (int nj = 0; nj < 8; nj++) {
            sf[nj][0] = ex2(sf[nj][0] - m0);
            sf[nj][1] = ex2(sf[nj][1] - m0);
            sf[nj][2] = ex2(sf[nj][2] - m1);
            sf[nj][3] = ex2(sf[nj][3] - m1);
            s0 += sf[nj][0] + sf[nj][1];
            s1 += sf[nj][2] + sf[nj][3];
        }
        s0 += __shfl_xor_sync(0xffffffffu, s0, 1);
        s0 += __shfl_xor_sync(0xffffffffu, s0, 2);
        s1 += __shfl_xor_sync(0xffffffffu, s1, 1);
        s1 += __shfl_xor_sync(0xffffffffu, s1, 2);
        l0 = l0 * al0 + s0;
        l1 = l1 * al1 + s1;

#pragma unroll
        for (int nj = 0; nj < 8; nj++) {
            oacc[nj][0] *= al0; oacc[nj][1] *= al0;
            oacc[nj][2] *= al1; oacc[nj][3] *= al1;
        }

#pragma unroll
        for (int ks = 0; ks < 4; ks++) {
            uint32_t pah[4], pal[4];
            split2(sf[2 * ks][0],     sf[2 * ks][1],     pah[0], pal[0]);
            split2(sf[2 * ks][2],     sf[2 * ks][3],     pah[1], pal[1]);
            split2(sf[2 * ks + 1][0], sf[2 * ks + 1][1], pah[2], pal[2]);
            split2(sf[2 * ks + 1][2], sf[2 * ks + 1][3], pah[3], pal[3]);
#pragma unroll
            for (int ntp = 0; ntp < 2; ntp++) {
                uint32_t vfh[2][4], vfl[2][4];
#pragma unroll
                for (int nt2 = 0; nt2 < 2; nt2++) {
                    uint32_t va = sV + (ks * 16 + vrow) * AP + (ntp * 2 + nt2) * 32 + vb16;
                    ldsm4t(vfh[nt2], va);
                    ldsm4t(vfl[nt2], va + KT_B);
                }
#pragma unroll
                for (int term = 0; term < 3; term++) {
                    const uint32_t* a = (term == 2) ? pal : pah;
#pragma unroll
                    for (int nt2 = 0; nt2 < 2; nt2++) {
#pragma unroll
                        for (int sel = 0; sel < 2; sel++) {
                            const int nj = (ntp * 2 + nt2) * 2 + sel;
                            const uint32_t b0 = (term == 1) ? vfl[nt2][sel]     : vfh[nt2][sel];
                            const uint32_t b1 = (term == 1) ? vfl[nt2][sel + 2] : vfh[nt2][sel + 2];
                            mma16816(oacc[nj], a, b0, b1);
                        }
                    }
                }
            }
        }
        __syncthreads();

        if (kb + 2 < nkb) {
            issue_kv(sKV + (kb & 1) * ASTG_B, Kh, Kl, Vh, Vl, base, kb + 2, tid);
            CP_COMMIT();
        }
    }

    // ---- epilogue ----
    const float inv0 = 1.0f / l0;
    const float inv1 = 1.0f / l1;
    const int b = bh >> 4, h = bh & 15;
    const size_t row0 = (size_t)(b * SS + r0) * DM;
    const size_t row1 = (size_t)(b * SS + r1) * DM;
#pragma unroll
    for (int nj = 0; nj < 8; nj++) {
        const int e = h * 64 + nj * 8 + 2 * t;
        uint32_t uh, ul;
        split2(oacc[nj][0] * inv0, oacc[nj][1] * inv0, uh, ul);
        *(uint32_t*)&AOh[row0 + e] = uh;
        *(uint32_t*)&AOl[row0 + e] = ul;
        split2(oacc[nj][2] * inv1, oacc[nj][3] * inv1, uh, ul);
        *(uint32_t*)&AOh[row1 + e] = uh;
        *(uint32_t*)&AOl[row1 + e] = ul;
    }
}

// ---------------------------------------------------------------------------
extern "C" void kernel_launch(void* const* d_in, const int* in_sizes, int n_in,
                              void* d_out, int out_size)
{
    const float* x  = (const float*)d_in[0];
    const float* Wq = (const float*)d_in[1];
    const float* Wk = (const float*)d_in[2];
    const float* Wv = (const float*)d_in[3];
    const float* Wo = (const float*)d_in[4];
    const int*   tp = (const int*)  d_in[5];
    float* out = (float*)d_out;

    float* gRope;
    __nv_bfloat16 *xh, *xl, *wh, *wl, *aoh, *aol;
    __nv_bfloat16 *qh, *ql, *kh, *kl, *vh, *vl;
    cudaGetSymbolAddress((void**)&gRope, g_rope);
    cudaGetSymbolAddress((void**)&xh,  g_xh);
    cudaGetSymbolAddress((void**)&xl,  g_xl);
    cudaGetSymbolAddress((void**)&wh,  g_wh);
    cudaGetSymbolAddress((void**)&wl,  g_wl);
    cudaGetSymbolAddress((void**)&aoh, g_aoh);
    cudaGetSymbolAddress((void**)&aol, g_aol);
    cudaGetSymbolAddress((void**)&qh,  g_Qh);
    cudaGetSymbolAddress((void**)&ql,  g_Ql);
    cudaGetSymbolAddress((void**)&kh,  g_Kh);
    cudaGetSymbolAddress((void**)&kl,  g_Kl);
    cudaGetSymbolAddress((void**)&vh,  g_Vh);
    cudaGetSymbolAddress((void**)&vl,  g_Vl);

    cudaFuncSetAttribute(gemm_mma, cudaFuncAttributeMaxDynamicSharedMemorySize, GSMEM);
    cudaFuncSetAttribute(attn_mma, cudaFuncAttributeMaxDynamicSharedMemorySize, ASMEM);

    const int nx4 = MTOT * DM / 4;
    const int nw4 = DM * DM / 4;
    split_kernel<<<nx4 / 256, 256>>>(x, xh, xl, nx4);
    dim3 wgrid(nw4 / 256, 4);
    split_w_kernel<<<wgrid, 256>>>(Wq, Wk, Wv, Wo, wh, wl);
    rope_init_kernel<<<SS * 32 / 256, 256>>>(tp, gRope);

    dim3 qkvgrid(MTOT / 128, 24);   // (64, 24)
    gemm_mma<<<qkvgrid, 256, GSMEM>>>(xh, xl, wh, wl, nullptr,
                                      qh, ql, kh, kl, vh, vl, gRope, 0);

    attn_mma<<<1024, 256, ASMEM>>>(qh, ql, kh, kl, vh, vl, aoh, aol);

    dim3 wogrid(MTOT / 128, 8);     // (64, 8)
    gemm_mma<<<wogrid, 256, GSMEM>>>(aoh, aol, wh, wl, out,
                                     qh, ql, kh, kl, vh, vl, gRope, 1);
}

// round 13
// speedup vs baseline: 2.1951x; 2.0540x over previous
#include <cuda_runtime.h>
#include <cuda_bf16.h>
#include <cuda_fp16.h>
#include <math.h>
#include <math_constants.h>
#include <cstdint>

#define BB 4
#define SS 2048
#define DM 1024
#define HH 16
#define DKK 64
#define MTOT (BB*SS)   // 8192

// ---------------- scratch (allocation-free) ----------------
__device__ __half g_xf[(size_t)MTOT*DM];
__device__ __half g_wf[(size_t)4*DM*DM];
__device__ __half g_vf[(size_t)BB*HH*SS*DKK];
__device__ __half g_aof[(size_t)MTOT*DM];
__device__ __nv_bfloat16 g_Qh[(size_t)BB*HH*SS*DKK], g_Ql[(size_t)BB*HH*SS*DKK];
__device__ __nv_bfloat16 g_Kh[(size_t)BB*HH*SS*DKK], g_Kl[(size_t)BB*HH*SS*DKK];
__device__ float g_rope[SS*64];   // [s][0..31]=cos, [s][32..63]=sin

#define ASCALE 0.1803368801111244f   // 1/sqrt(64)*log2(e)

// ---------------- PTX helpers ----------------
__device__ __forceinline__ uint32_t smem_to_u32(const void* p) {
    uint32_t a;
    asm("{ .reg .u64 t; cvta.to.shared.u64 t, %1; cvt.u32.u64 %0, t; }"
        : "=r"(a) : "l"(p));
    return a;
}
__device__ __forceinline__ void cp16(uint32_t dst, const void* src) {
    asm volatile("cp.async.cg.shared.global [%0], [%1], 16;"
                 :: "r"(dst), "l"(src) : "memory");
}
#define CP_COMMIT() asm volatile("cp.async.commit_group;" ::: "memory")
#define CP_WAIT1()  asm volatile("cp.async.wait_group 1;"  ::: "memory")
#define CP_WAIT0()  asm volatile("cp.async.wait_group 0;"  ::: "memory")

__device__ __forceinline__ void ldsm4(uint32_t* r, uint32_t addr) {
    asm volatile("ldmatrix.sync.aligned.m8n8.x4.shared.b16 {%0,%1,%2,%3}, [%4];"
                 : "=r"(r[0]), "=r"(r[1]), "=r"(r[2]), "=r"(r[3]) : "r"(addr));
}
__device__ __forceinline__ void ldsm4t(uint32_t* r, uint32_t addr) {
    asm volatile("ldmatrix.sync.aligned.m8n8.x4.trans.shared.b16 {%0,%1,%2,%3}, [%4];"
                 : "=r"(r[0]), "=r"(r[1]), "=r"(r[2]), "=r"(r[3]) : "r"(addr));
}
// bf16 mma (score path)
__device__ __forceinline__ void mma16816(float* d, const uint32_t* a,
                                         uint32_t b0, uint32_t b1) {
    asm volatile("mma.sync.aligned.m16n8k16.row.col.f32.bf16.bf16.f32 "
                 "{%0,%1,%2,%3}, {%4,%5,%6,%7}, {%8,%9}, {%0,%1,%2,%3};"
                 : "+f"(d[0]), "+f"(d[1]), "+f"(d[2]), "+f"(d[3])
                 : "r"(a[0]), "r"(a[1]), "r"(a[2]), "r"(a[3]), "r"(b0), "r"(b1));
}
// fp16 mma (projections / PV / Wo)
__device__ __forceinline__ void mma16816h(float* d, const uint32_t* a,
                                          uint32_t b0, uint32_t b1) {
    asm volatile("mma.sync.aligned.m16n8k16.row.col.f32.f16.f16.f32 "
                 "{%0,%1,%2,%3}, {%4,%5,%6,%7}, {%8,%9}, {%0,%1,%2,%3};"
                 : "+f"(d[0]), "+f"(d[1]), "+f"(d[2]), "+f"(d[3])
                 : "r"(a[0]), "r"(a[1]), "r"(a[2]), "r"(a[3]), "r"(b0), "r"(b1));
}
__device__ __forceinline__ float ex2(float x) {
    float y;
    asm("ex2.approx.f32 %0, %1;" : "=f"(y) : "f"(x));
    return y;
}
__device__ __forceinline__ uint32_t packbf(float lo, float hi) {
    uint32_t r;
    asm("cvt.rn.bf16x2.f32 %0, %1, %2;" : "=r"(r) : "f"(hi), "f"(lo));
    return r;
}
__device__ __forceinline__ uint32_t packhf(float lo, float hi) {
    uint32_t r;
    asm("cvt.rn.f16x2.f32 %0, %1, %2;" : "=r"(r) : "f"(hi), "f"(lo));
    return r;
}
__device__ __forceinline__ void split2(float d0, float d1, uint32_t& uh, uint32_t& ul) {
    uh = packbf(d0, d1);
    float h0 = __uint_as_float(uh << 16);
    float h1 = __uint_as_float(uh & 0xffff0000u);
    ul = packbf(d0 - h0, d1 - h1);
}

// ---------------------------------------------------------------------------
// fp32 -> fp16 conversions
// ---------------------------------------------------------------------------
__global__ void cvt_kernel(const float* __restrict__ src, __half* __restrict__ dst, int n4)
{
    int i = blockIdx.x * blockDim.x + threadIdx.x;
    if (i >= n4) return;
    float4 v = ((const float4*)src)[i];
    ((uint2*)dst)[i] = make_uint2(packhf(v.x, v.y), packhf(v.z, v.w));
}

__global__ void cvt_w_kernel(const float* __restrict__ w0, const float* __restrict__ w1,
                             const float* __restrict__ w2, const float* __restrict__ w3,
                             __half* __restrict__ dst)
{
    const int wsel = blockIdx.y;
    const float* src = (wsel == 0) ? w0 : (wsel == 1) ? w1 : (wsel == 2) ? w2 : w3;
    size_t off = (size_t)wsel * (DM * DM / 4);
    int i = blockIdx.x * blockDim.x + threadIdx.x;
    float4 v = ((const float4*)src)[i];
    ((uint2*)dst)[off + i] = make_uint2(packhf(v.x, v.y), packhf(v.z, v.w));
}

__global__ void rope_init_kernel(const int* __restrict__ tokpos, float* __restrict__ rope)
{
    int idx = blockIdx.x * blockDim.x + threadIdx.x;
    int s = idx >> 5, p = idx & 31;
    float fr = (float)exp2(-(double)p * (13.287712379549449 / 32.0));
    float ang = (float)tokpos[s] * fr;
    float sn, cs;
    sincosf(ang, &sn, &cs);
    rope[s * 64 + p] = cs;
    rope[s * 64 + 32 + p] = sn;
}

// ---------------------------------------------------------------------------
// fp16 single-term GEMM: C[m,e] = sum_d A[m,d]*W[e,d]  (fp32 accumulate)
// CTA 128x128, BK=32, 8 warps 4x2 (warp tile 32x64), 2-stage, 2 CTAs/SM,
// single sync per K-chunk (round-10 validated structure).
// wsel 0: RoPE*ASCALE -> Q bf16 hi/lo; 1: RoPE -> K bf16 hi/lo;
// wsel 2: -> V fp16; 3: fp32 -> out.
// ---------------------------------------------------------------------------
#define GP      40
#define TILE_B  (128*GP*2)         // 10240 bytes (128 rows x 80B pitch)
#define STAGE_B (2*TILE_B)         // 20480 (A | B)
#define GSMEM   (2*STAGE_B)        // 40960

__device__ __forceinline__ void issue_stage(uint32_t sdst,
    const __half* __restrict__ A, const __half* __restrict__ B,
    int m0, int n0, int kc, int tid)
{
    const int colb = kc * 64;
#pragma unroll
    for (int it = 0; it < 2; it++) {
        int idx = tid + it * 256;
        int row = idx >> 2;
        int ch  = (idx & 3) * 16;
        uint32_t soff = row * 80 + ch;
        cp16(sdst + soff,          (const char*)(A + (size_t)(m0 + row) * DM) + colb + ch);
        cp16(sdst + TILE_B + soff, (const char*)(B + (size_t)(n0 + row) * DM) + colb + ch);
    }
}

__global__ __launch_bounds__(256, 2)
void gemm_h(const __half* __restrict__ A, const __half* __restrict__ WBase,
            float* __restrict__ out,
            __nv_bfloat16* __restrict__ qh, __nv_bfloat16* __restrict__ ql,
            __nv_bfloat16* __restrict__ kh, __nv_bfloat16* __restrict__ kl,
            __half* __restrict__ vf,
            const float* __restrict__ rope, int wo)
{
    extern __shared__ char smc[];
    const uint32_t sbase = smem_to_u32(smc);

    const int tid  = threadIdx.x;
    const int wid  = tid >> 5;
    const int lane = tid & 31;
    const int m0 = blockIdx.x * 128;
    const int by = blockIdx.y;
    const int wsel = wo ? 3 : (by >> 3);
    const int n0 = wo ? by * 128 : (by & 7) * 128;
    const __half* B = WBase + (size_t)wsel * DM * DM;

    const int wm = (wid & 3) * 32;
    const int wn = (wid >> 2) * 64;

    float acc[2][8][4];
#pragma unroll
    for (int i = 0; i < 2; i++)
#pragma unroll
        for (int j = 0; j < 8; j++)
#pragma unroll
            for (int q = 0; q < 4; q++) acc[i][j][q] = 0.f;

    const uint32_t lrow = (lane & 7) + ((lane >> 3) & 1) * 8;
    const uint32_t kbl  = ((lane >> 4) & 1) * 16;

    issue_stage(sbase, A, B, m0, n0, 0, tid);
    CP_COMMIT();

    const int NKC = DM / 32;   // 32
    for (int kc = 0; kc < NKC; kc++) {
        CP_WAIT0();
        __syncthreads();
        if (kc + 1 < NKC) {
            issue_stage(sbase + ((kc + 1) & 1) * STAGE_B, A, B, m0, n0, kc + 1, tid);
            CP_COMMIT();
        }

        const uint32_t sb = sbase + (kc & 1) * STAGE_B;
#pragma unroll
        for (int ks = 0; ks < 2; ks++) {
            const uint32_t kb = ks * 32 + kbl;
            uint32_t a0[4], a1[4];
            const uint32_t aadr = sb + (wm + lrow) * 80 + kb;
            ldsm4(a0, aadr);
            ldsm4(a1, aadr + 16 * 80);
#pragma unroll
            for (int nb = 0; nb < 4; nb++) {
                uint32_t bf[4];
                const uint32_t badr = sb + TILE_B + (wn + nb * 16 + lrow) * 80 + kb;
                ldsm4(bf, badr);
#pragma unroll
                for (int sel = 0; sel < 2; sel++) {
                    const int nj = nb * 2 + sel;
                    mma16816h(acc[0][nj], a0, bf[sel], bf[sel + 2]);
                    mma16816h(acc[1][nj], a1, bf[sel], bf[sel + 2]);
                }
            }
        }
    }

    // ---- epilogue ----
    const int g = lane >> 2;
    const int t2 = (lane & 3) * 2;
#pragma unroll
    for (int mi = 0; mi < 2; mi++) {
#pragma unroll
        for (int half = 0; half < 2; half++) {
            const int r = m0 + wm + mi * 16 + half * 8 + g;
            const int b = r >> 11;
            const int s = r & 2047;
#pragma unroll
            for (int nj = 0; nj < 8; nj++) {
                const int e = n0 + wn + nj * 8 + t2;
                float d0 = acc[mi][nj][half * 2 + 0];
                float d1 = acc[mi][nj][half * 2 + 1];
                if (wsel == 3) {
                    *(float2*)&out[(size_t)r * DM + e] = make_float2(d0, d1);
                } else {
                    const int h  = e >> 6;
                    const int dk = e & 63;
                    size_t idx = ((size_t)(b * HH + h) * SS + s) * DKK + dk;
                    if (wsel == 2) {
                        *(uint32_t*)&vf[idx] = packhf(d0, d1);
                    } else {
                        const int p = dk >> 1;
                        float cs = __ldg(&rope[s * 64 + p]);
                        float sn = __ldg(&rope[s * 64 + 32 + p]);
                        float r0 = d0 * cs - d1 * sn;
                        float r1 = d0 * sn + d1 * cs;
                        if (wsel == 0) { r0 *= ASCALE; r1 *= ASCALE; }
                        uint32_t uh, ul;
                        split2(r0, r1, uh, ul);
                        __nv_bfloat16* oh = (wsel == 0) ? qh : kh;
                        __nv_bfloat16* ol = (wsel == 0) ? ql : kl;
                        *(uint32_t*)&oh[idx] = uh;
                        *(uint32_t*)&ol[idx] = ul;
                    }
                }
            }
        }
    }
}

// ---------------------------------------------------------------------------
// Flash attention: S-phase bf16x3 (exponent-sensitive), PV-phase fp16 single.
// 2-stage KV, 2 CTAs/SM.  KV stage = Kh | Kl | Vf (3 tiles).
// ---------------------------------------------------------------------------
#define AP      144
#define QT_B    (128*AP)      // 18432
#define KT_B    (64*AP)       // 9216
#define ASTG_B  (3*KT_B)      // 27648
#define ASMEM   (2*QT_B + 2*ASTG_B)   // 92160

__device__ __forceinline__ void issue_kv(uint32_t dst,
    const __nv_bfloat16* __restrict__ Kh, const __nv_bfloat16* __restrict__ Kl,
    const __half* __restrict__ Vf,
    size_t base, int kb, int tid)
{
#pragma unroll
    for (int it = 0; it < 6; it++) {
        int f   = tid + it * 256;       // 0..1535
        int ten = f >> 9;               // 0,1,2
        int row = (f >> 3) & 63;
        int ch  = f & 7;
        const void* sp;
        if (ten == 0)      sp = Kh + base + (size_t)(kb * 64 + row) * DKK + ch * 8;
        else if (ten == 1) sp = Kl + base + (size_t)(kb * 64 + row) * DKK + ch * 8;
        else               sp = Vf + base + (size_t)(kb * 64 + row) * DKK + ch * 8;
        cp16(dst + ten * KT_B + row * AP + ch * 16, sp);
    }
}

__global__ __launch_bounds__(256, 2)
void attn_mma(const __nv_bfloat16* __restrict__ Qh, const __nv_bfloat16* __restrict__ Ql,
              const __nv_bfloat16* __restrict__ Kh, const __nv_bfloat16* __restrict__ Kl,
              const __half* __restrict__ Vf,
              __half* __restrict__ AOf)
{
    extern __shared__ char smc[];
    const uint32_t sb = smem_to_u32(smc);
    const uint32_t sQ  = sb;
    const uint32_t sKV = sb + 2 * QT_B;

    const int tid  = threadIdx.x;
    const int wid  = tid >> 5;
    const int lane = tid & 31;
    const int g = lane >> 2;
    const int t = lane & 3;

    const int qb = 15 - (blockIdx.x >> 6);    // heavy q-blocks first
    const int bh = blockIdx.x & 63;
    const size_t base = (size_t)bh * SS * DKK;
    const int nkb = 2 * qb + 2;

    const float NINF = __int_as_float(0xff800000);

#pragma unroll
    for (int it = 0; it < 8; it++) {
        int f   = tid + it * 256;
        int ten = f >> 10;
        int row = (f >> 3) & 127;
        int ch  = f & 7;
        const __nv_bfloat16* sp = (ten ? Ql : Qh)
            + base + (size_t)(qb * 128 + row) * DKK + ch * 8;
        cp16(sQ + ten * QT_B + row * AP + ch * 16, sp);
    }
    issue_kv(sKV, Kh, Kl, Vf, base, 0, tid);
    CP_COMMIT();
    issue_kv(sKV + ASTG_B, Kh, Kl, Vf, base, 1, tid);
    CP_COMMIT();

    CP_WAIT1();
    __syncthreads();

    const uint32_t lrow = (lane & 7) + ((lane >> 3) & 1) * 8;
    const uint32_t kb16 = ((lane >> 4) & 1) * 16;
    uint32_t qfh[4][4], qfl[4][4];
#pragma unroll
    for (int ks = 0; ks < 4; ks++) {
        uint32_t a = sQ + (wid * 16 + lrow) * AP + ks * 32 + kb16;
        ldsm4(qfh[ks], a);
        ldsm4(qfl[ks], a + QT_B);
    }

    float oacc[8][4];
#pragma unroll
    for (int nj = 0; nj < 8; nj++)
#pragma unroll
        for (int q = 0; q < 4; q++) oacc[nj][q] = 0.f;
    float m0 = NINF, m1 = NINF, l0 = 0.f, l1 = 0.f;

    const int r0 = qb * 128 + wid * 16 + g;
    const int r1 = r0 + 8;

    const uint32_t vrow = (lane & 7) + ((lane >> 4) & 1) * 8;
    const uint32_t vb16 = ((lane >> 3) & 1) * 16;

    for (int kb = 0; kb < nkb; kb++) {
        if (kb + 1 < nkb) CP_WAIT1(); else CP_WAIT0();
        __syncthreads();

        const uint32_t sK = sKV + (kb & 1) * ASTG_B;
        const uint32_t sV = sK + 2 * KT_B;

        // ---- S = Qh*Kh + Qh*Kl + Ql*Kh (bf16x3) ----
        float sf[8][4];
#pragma unroll
        for (int nj = 0; nj < 8; nj++)
#pragma unroll
            for (int q = 0; q < 4; q++) sf[nj][q] = 0.f;

#pragma unroll
        for (int ks = 0; ks < 4; ks++) {
#pragma unroll
            for (int ntp = 0; ntp < 2; ntp++) {
                uint32_t kfh[2][4], kfl[2][4];
#pragma unroll
                for (int nt2 = 0; nt2 < 2; nt2++) {
                    uint32_t ba = sK + ((ntp * 2 + nt2) * 16 + lrow) * AP + ks * 32 + kb16;
                    ldsm4(kfh[nt2], ba);
                    ldsm4(kfl[nt2], ba + KT_B);
                }
#pragma unroll
                for (int term = 0; term < 3; term++) {
                    const uint32_t* a = (term == 2) ? qfl[ks] : qfh[ks];
#pragma unroll
                    for (int nt2 = 0; nt2 < 2; nt2++) {
#pragma unroll
                        for (int sel = 0; sel < 2; sel++) {
                            const int nj = (ntp * 2 + nt2) * 2 + sel;
                            const uint32_t b0 = (term == 1) ? kfl[nt2][sel]     : kfh[nt2][sel];
                            const uint32_t b1 = (term == 1) ? kfl[nt2][sel + 2] : kfh[nt2][sel + 2];
                            mma16816(sf[nj], a, b0, b1);
                        }
                    }
                }
            }
        }

        // ---- causal mask ----
        if (kb >= 2 * qb) {
#pragma unroll
            for (int nj = 0; nj < 8; nj++) {
                int c0 = kb * 64 + nj * 8 + 2 * t;
                if (c0 > r0)     sf[nj][0] = NINF;
                if (c0 + 1 > r0) sf[nj][1] = NINF;
                if (c0 > r1)     sf[nj][2] = NINF;
                if (c0 + 1 > r1) sf[nj][3] = NINF;
            }
        }

        // ---- online softmax (base-2 domain) ----
        float mx0 = sf[0][0], mx1 = sf[0][2];
#pragma unroll
        for (int nj = 0; nj < 8; nj++) {
            mx0 = fmaxf(mx0, fmaxf(sf[nj][0], sf[nj][1]));
            mx1 = fmaxf(mx1, fmaxf(sf[nj][2], sf[nj][3]));
        }
        mx0 = fmaxf(mx0, __shfl_xor_sync(0xffffffffu, mx0, 1));
        mx0 = fmaxf(mx0, __shfl_xor_sync(0xffffffffu, mx0, 2));
        mx1 = fmaxf(mx1, __shfl_xor_sync(0xffffffffu, mx1, 1));
        mx1 = fmaxf(mx1, __shfl_xor_sync(0xffffffffu, mx1, 2));
        float mn0 = fmaxf(m0, mx0), mn1 = fmaxf(m1, mx1);
        float al0 = ex2(m0 - mn0), al1 = ex2(m1 - mn1);
        m0 = mn0; m1 = mn1;

        float s0 = 0.f, s1 = 0.f;
#pragma unroll
        for (int nj = 0; nj < 8; nj++) {
            sf[nj][0] = ex2(sf[nj][0] - m0);
            sf[nj][1] = ex2(sf[nj][1] - m0);
            sf[nj][2] = ex2(sf[nj][2] - m1);
            sf[nj][3] = ex2(sf[nj][3] - m1);
            s0 += sf[nj][0] + sf[nj][1];
            s1 += sf[nj][2] + sf[nj][3];
        }
        s0 += __shfl_xor_sync(0xffffffffu, s0, 1);
        s0 += __shfl_xor_sync(0xffffffffu, s0, 2);
        s1 += __shfl_xor_sync(0xffffffffu, s1, 1);
        s1 += __shfl_xor_sync(0xffffffffu, s1, 2);
        l0 = l0 * al0 + s0;
        l1 = l1 * al1 + s1;

#pragma unroll
        for (int nj = 0; nj < 8; nj++) {
            oacc[nj][0] *= al0; oacc[nj][1] *= al0;
            oacc[nj][2] *= al1; oacc[nj][3] *= al1;
        }

        // ---- O += P * V  (fp16 single-term) ----
#pragma unroll
        for (int ks = 0; ks < 4; ks++) {
            uint32_t pa[4];
            pa[0] = packhf(sf[2 * ks][0],     sf[2 * ks][1]);
            pa[1] = packhf(sf[2 * ks][2],     sf[2 * ks][3]);
            pa[2] = packhf(sf[2 * ks + 1][0], sf[2 * ks + 1][1]);
            pa[3] = packhf(sf[2 * ks + 1][2], sf[2 * ks + 1][3]);
#pragma unroll
            for (int ntp = 0; ntp < 2; ntp++) {
                uint32_t vfr[2][4];
#pragma unroll
                for (int nt2 = 0; nt2 < 2; nt2++) {
                    uint32_t va = sV + (ks * 16 + vrow) * AP + (ntp * 2 + nt2) * 32 + vb16;
                    ldsm4t(vfr[nt2], va);
                }
#pragma unroll
                for (int nt2 = 0; nt2 < 2; nt2++) {
#pragma unroll
                    for (int sel = 0; sel < 2; sel++) {
                        const int nj = (ntp * 2 + nt2) * 2 + sel;
                        mma16816h(oacc[nj], pa, vfr[nt2][sel], vfr[nt2][sel + 2]);
                    }
                }
            }
        }
        __syncthreads();

        if (kb + 2 < nkb) {
            issue_kv(sKV + (kb & 1) * ASTG_B, Kh, Kl, Vf, base, kb + 2, tid);
            CP_COMMIT();
        }
    }

    // ---- epilogue: fp16 AO at [b*S+s][h*64+dk] ----
    const float inv0 = 1.0f / l0;
    const float inv1 = 1.0f / l1;
    const int b = bh >> 4, h = bh & 15;
    const size_t row0 = (size_t)(b * SS + r0) * DM;
    const size_t row1 = (size_t)(b * SS + r1) * DM;
#pragma unroll
    for (int nj = 0; nj < 8; nj++) {
        const int e = h * 64 + nj * 8 + 2 * t;
        *(uint32_t*)&AOf[row0 + e] = packhf(oacc[nj][0] * inv0, oacc[nj][1] * inv0);
        *(uint32_t*)&AOf[row1 + e] = packhf(oacc[nj][2] * inv1, oacc[nj][3] * inv1);
    }
}

// ---------------------------------------------------------------------------
extern "C" void kernel_launch(void* const* d_in, const int* in_sizes, int n_in,
                              void* d_out, int out_size)
{
    const float* x  = (const float*)d_in[0];
    const float* Wq = (const float*)d_in[1];
    const float* Wk = (const float*)d_in[2];
    const float* Wv = (const float*)d_in[3];
    const float* Wo = (const float*)d_in[4];
    const int*   tp = (const int*)  d_in[5];
    float* out = (float*)d_out;

    float* gRope;
    __half *xf, *wf, *vf, *aof;
    __nv_bfloat16 *qh, *ql, *kh, *kl;
    cudaGetSymbolAddress((void**)&gRope, g_rope);
    cudaGetSymbolAddress((void**)&xf,  g_xf);
    cudaGetSymbolAddress((void**)&wf,  g_wf);
    cudaGetSymbolAddress((void**)&vf,  g_vf);
    cudaGetSymbolAddress((void**)&aof, g_aof);
    cudaGetSymbolAddress((void**)&qh,  g_Qh);
    cudaGetSymbolAddress((void**)&ql,  g_Ql);
    cudaGetSymbolAddress((void**)&kh,  g_Kh);
    cudaGetSymbolAddress((void**)&kl,  g_Kl);

    cudaFuncSetAttribute(gemm_h,   cudaFuncAttributeMaxDynamicSharedMemorySize, GSMEM);
    cudaFuncSetAttribute(attn_mma, cudaFuncAttributeMaxDynamicSharedMemorySize, ASMEM);

    const int nx4 = MTOT * DM / 4;
    const int nw4 = DM * DM / 4;
    cvt_kernel<<<nx4 / 256, 256>>>(x, xf, nx4);
    dim3 wgrid(nw4 / 256, 4);
    cvt_w_kernel<<<wgrid, 256>>>(Wq, Wk, Wv, Wo, wf);
    rope_init_kernel<<<SS * 32 / 256, 256>>>(tp, gRope);

    dim3 qkvgrid(MTOT / 128, 24);   // (64, 24)
    gemm_h<<<qkvgrid, 256, GSMEM>>>(xf, wf, nullptr,
                                    qh, ql, kh, kl, vf, gRope, 0);

    attn_mma<<<1024, 256, ASMEM>>>(qh, ql, kh, kl, vf, aof);

    dim3 wogrid(MTOT / 128, 8);     // (64, 8)
    gemm_h<<<wogrid, 256, GSMEM>>>(aof, wf, out,
                                   qh, ql, kh, kl, vf, gRope, 1);
}